// round 4
// baseline (speedup 1.0000x reference)
#include <cuda_runtime.h>

// VectorQuantizer via warp-level tf32 mma.sync + exact fp32 re-score.
// inputs [32,64,64,64] f32 NCHW, weight [512,64] f32.
// out[0..N*D) = fl(x + fl(q-x)) NCHW; out[N*D..) = 1.25*mean((q-x)^2).

#define KCODES  512
#define DDIM    64
#define HWSZ    4096
#define NTOT    131072
#define TILE_M  256
#define NTILES  (NTOT / TILE_M)   // 512
#define NTHREADS 256
#define CAP     16

typedef unsigned int u32;
typedef unsigned long long u64;
typedef unsigned short u16;

__device__ float g_partials[NTILES];

// ---- smem layout (bytes) ----
#define BSTRIDE  520                              // u32 elems per k-row (pad: bank = 8k+n)
#define OFF_B    0                                // tf32 codebook [64][520] u32: 133120 B
#define OFF_A    (64 * BSTRIDE * 4)               // fp32 x-tile [256][65]: 66560 B
#define ASTRIDE  65
#define OFF_SWN  (OFF_A + TILE_M * ASTRIDE * 4)   // 512 f32 norms
#define OFF_SX   (OFF_SWN + 2048)                 // 256 f32 ||x||^2 (reused for loss)
#define OFF_BIDX (OFF_SX + 1024)                  // 256 u16
#define OFF_OVF  (OFF_BIDX + 512)                 // 256 u8
#define SMEM_TOTAL (OFF_OVF + 256)                // 203520 B

// ---- helpers ----
__device__ __forceinline__ u32 f2tf32(float f) {
    u32 r; asm("cvt.rna.tf32.f32 %0, %1;" : "=r"(r) : "f"(f)); return r;
}
__device__ __forceinline__ u64 ffma2(u64 a, u64 b, u64 c) {
    u64 d; asm("fma.rn.f32x2 %0, %1, %2, %3;" : "=l"(d) : "l"(a), "l"(b), "l"(c)); return d;
}
__device__ __forceinline__ u64 fadd2(u64 a, u64 b) {
    u64 d; asm("add.rn.f32x2 %0, %1, %2;" : "=l"(d) : "l"(a), "l"(b)); return d;
}
__device__ __forceinline__ u64 pack2(float lo, float hi) {
    u64 d; asm("mov.b64 %0, {%1, %2};" : "=l"(d) : "f"(lo), "f"(hi)); return d;
}
__device__ __forceinline__ void unpack2(u64 v, float& lo, float& hi) {
    asm("mov.b64 {%0, %1}, %2;" : "=f"(lo), "=f"(hi) : "l"(v));
}

#define MMA4(c, a, b0, b1)                                                      \
    asm volatile("mma.sync.aligned.m16n8k8.row.col.f32.tf32.tf32.f32 "          \
                 "{%0,%1,%2,%3}, {%4,%5,%6,%7}, {%8,%9}, {%0,%1,%2,%3};"        \
                 : "+f"((c)[0]), "+f"((c)[1]), "+f"((c)[2]), "+f"((c)[3])       \
                 : "r"((a)[0]), "r"((a)[1]), "r"((a)[2]), "r"((a)[3]),          \
                   "r"(b0), "r"(b1))

// exact fp32 score, bit-identical to the round-2 passing pipeline:
// 4 interleaved f32x2 fma chains, (a0+a1),(a2+a3),sum, lo+hi,
// then d = fl( fl(sx + swn) - fl(2*dot) ).
__device__ __forceinline__ float exact_d(const float* __restrict__ xrow,
                                         const float* __restrict__ wrow,
                                         float sx, float swn_k) {
    u64 a0 = 0ull, a1 = 0ull, a2 = 0ull, a3 = 0ull;
    #pragma unroll
    for (int j = 0; j < DDIM / 2; j += 4) {
        u64 x0 = pack2(xrow[2*(j+0)], xrow[2*(j+0)+1]);
        u64 x1 = pack2(xrow[2*(j+1)], xrow[2*(j+1)+1]);
        u64 x2 = pack2(xrow[2*(j+2)], xrow[2*(j+2)+1]);
        u64 x3 = pack2(xrow[2*(j+3)], xrow[2*(j+3)+1]);
        u64 w0 = pack2(wrow[2*(j+0)], wrow[2*(j+0)+1]);
        u64 w1 = pack2(wrow[2*(j+1)], wrow[2*(j+1)+1]);
        u64 w2 = pack2(wrow[2*(j+2)], wrow[2*(j+2)+1]);
        u64 w3 = pack2(wrow[2*(j+3)], wrow[2*(j+3)+1]);
        a0 = ffma2(x0, w0, a0);
        a1 = ffma2(x1, w1, a1);
        a2 = ffma2(x2, w2, a2);
        a3 = ffma2(x3, w3, a3);
    }
    a0 = fadd2(a0, a1);
    a2 = fadd2(a2, a3);
    a0 = fadd2(a0, a2);
    float lo, hi;
    unpack2(a0, lo, hi);
    float dot = __fadd_rn(lo, hi);
    float t = __fadd_rn(sx, swn_k);
    return __fsub_rn(t, __fmul_rn(2.0f, dot));
}

extern __shared__ char smem[];

__global__ void __launch_bounds__(NTHREADS, 1)
vq_mma_kernel(const float* __restrict__ input,
              const float* __restrict__ weight,
              float* __restrict__ out)
{
    u32*   Bu    = (u32*)(smem + OFF_B);
    float* A32   = (float*)(smem + OFF_A);
    float* SWN   = (float*)(smem + OFF_SWN);
    float* SX    = (float*)(smem + OFF_SX);
    u16*   SBIDX = (u16*)(smem + OFF_BIDX);
    unsigned char* SOVF = (unsigned char*)(smem + OFF_OVF);

    const int tid = threadIdx.x;
    const int b   = blockIdx.x >> 4;
    const int hw0 = (blockIdx.x & 15) * TILE_M;
    const float* inb = input + (size_t)b * DDIM * HWSZ + hw0 + tid;

    // ---- stage A (fp32) + exact sequential sx ----
    float sx = 0.f;
    {
        float* arow = A32 + tid * ASTRIDE;
        #pragma unroll
        for (int c = 0; c < DDIM; c++) {
            float v = inb[(size_t)c * HWSZ];
            arow[c] = v;
            sx = __fadd_rn(sx, __fmul_rn(v, v));
        }
        SX[tid] = sx;
        SOVF[tid] = 0;
    }

    // ---- stage B (tf32, [k][n] padded) + exact sequential norms ----
    #pragma unroll
    for (int r = 0; r < 2; r++) {
        const int k = tid + r * NTHREADS;
        const float4* wr = (const float4*)(weight + (size_t)k * DDIM);
        float s = 0.f;
        #pragma unroll
        for (int c4 = 0; c4 < DDIM / 4; c4++) {
            float4 wv = wr[c4];
            s = __fadd_rn(s, __fmul_rn(wv.x, wv.x));
            s = __fadd_rn(s, __fmul_rn(wv.y, wv.y));
            s = __fadd_rn(s, __fmul_rn(wv.z, wv.z));
            s = __fadd_rn(s, __fmul_rn(wv.w, wv.w));
            int c = c4 * 4;
            Bu[(c + 0) * BSTRIDE + k] = f2tf32(wv.x);
            Bu[(c + 1) * BSTRIDE + k] = f2tf32(wv.y);
            Bu[(c + 2) * BSTRIDE + k] = f2tf32(wv.z);
            Bu[(c + 3) * BSTRIDE + k] = f2tf32(wv.w);
        }
        SWN[k] = s;
    }
    __syncthreads();

    // ---- A fragments (tf32) for this warp's 32 rows ----
    const int lane = tid & 31;
    const int g    = lane >> 2;     // group id (row within 8)
    const int tq   = lane & 3;      // thread-in-group (col pair / k)
    const int rbase = (tid >> 5) * 32;

    u32 afr[2][8][4];
    #pragma unroll
    for (int mt = 0; mt < 2; mt++) {
        const float* r0 = A32 + (rbase + mt * 16 + g) * ASTRIDE;
        const float* r1 = r0 + 8 * ASTRIDE;
        #pragma unroll
        for (int ks = 0; ks < 8; ks++) {
            afr[mt][ks][0] = f2tf32(r0[ks * 8 + tq]);
            afr[mt][ks][1] = f2tf32(r1[ks * 8 + tq]);
            afr[mt][ks][2] = f2tf32(r0[ks * 8 + tq + 4]);
            afr[mt][ks][3] = f2tf32(r1[ks * 8 + tq + 4]);
        }
    }

    // ---- per row-slot state: slot s = mt*2 + h, row = rbase + mt*16 + h*8 + g ----
    float mrg[4], bmin[4], th[4];
    float cd[4][CAP];
    u16   ck[4][CAP];
    int   cnt[4], ovf[4];
    #pragma unroll
    for (int s = 0; s < 4; s++) {
        int row = rbase + (s >> 1) * 16 + (s & 1) * 8 + g;
        float sxr = SX[row];
        mrg[s]  = fmaf(sqrtf(sxr), 3e-4f, 1e-4f);
        bmin[s] = 3.4e38f;
        th[s]   = 3.4e38f;
        cnt[s]  = 0;
        ovf[s]  = 0;
    }

    // ---- main loop: 32 chunks of 16 codes; score s~ = swn - 2*dot ----
    #pragma unroll 1
    for (int n2 = 0; n2 < 32; n2++) {
        const int nb = n2 * 16;
        float acc[2][2][4];
        #pragma unroll
        for (int i = 0; i < 2; i++)
            #pragma unroll
            for (int j = 0; j < 2; j++)
                #pragma unroll
                for (int e = 0; e < 4; e++) acc[i][j][e] = 0.f;

        #pragma unroll
        for (int ks = 0; ks < 8; ks++) {
            const u32* bk0 = Bu + (ks * 8 + tq) * BSTRIDE + nb + g;
            const u32* bk1 = bk0 + 4 * BSTRIDE;
            u32 b0a = bk0[0], b0b = bk0[8];
            u32 b1a = bk1[0], b1b = bk1[8];
            MMA4(acc[0][0], afr[0][ks], b0a, b1a);
            MMA4(acc[0][1], afr[0][ks], b0b, b1b);
            MMA4(acc[1][0], afr[1][ks], b0a, b1a);
            MMA4(acc[1][1], afr[1][ks], b0b, b1b);
        }

        float swnc[2][2];
        swnc[0][0] = SWN[nb + tq * 2];
        swnc[0][1] = SWN[nb + tq * 2 + 1];
        swnc[1][0] = SWN[nb + 8 + tq * 2];
        swnc[1][1] = SWN[nb + 8 + tq * 2 + 1];

        #pragma unroll
        for (int mt = 0; mt < 2; mt++)
        #pragma unroll
        for (int nn = 0; nn < 2; nn++)
        #pragma unroll
        for (int e = 0; e < 4; e++) {
            const int s   = mt * 2 + (e >> 1);
            const int col = nb + nn * 8 + tq * 2 + (e & 1);
            float dt = fmaf(-2.f, acc[mt][nn][e], swnc[nn][e & 1]);
            if (dt < bmin[s]) { bmin[s] = dt; th[s] = dt + mrg[s]; }
            if (dt <= th[s]) {
                if (cnt[s] == CAP) {           // compact against tightened threshold
                    int m = 0;
                    for (int i = 0; i < CAP; i++)
                        if (cd[s][i] <= th[s]) { cd[s][m] = cd[s][i]; ck[s][m] = ck[s][i]; m++; }
                    cnt[s] = m;
                }
                if (cnt[s] < CAP) { cd[s][cnt[s]] = dt; ck[s][cnt[s]] = (u16)col; cnt[s]++; }
                else ovf[s] = 1;
            }
        }
    }

    // ---- per slot: quad-merge min, filter, exact rescore, quad-merge argmin ----
    const unsigned FULL = 0xffffffffu;
    #pragma unroll
    for (int s = 0; s < 4; s++) {
        float bm = bmin[s];
        bm = fminf(bm, __shfl_xor_sync(FULL, bm, 1));
        bm = fminf(bm, __shfl_xor_sync(FULL, bm, 2));
        const float thf = bm + mrg[s];

        const int row = rbase + (s >> 1) * 16 + (s & 1) * 8 + g;
        const float* xrow = A32 + row * ASTRIDE;
        const float  sxr  = SX[row];

        float best = 3.4e38f;
        int   bk   = 0xffff;
        for (int i = 0; i < cnt[s]; i++) {
            if (cd[s][i] <= thf) {
                int k = ck[s][i];
                float d = exact_d(xrow, weight + (size_t)k * DDIM, sxr, SWN[k]);
                if (d < best) { best = d; bk = k; }   // ascending k => first-index ties
            }
        }
        #pragma unroll
        for (int off = 1; off <= 2; off <<= 1) {
            float d2 = __shfl_xor_sync(FULL, best, off);
            int   k2 = __shfl_xor_sync(FULL, bk, off);
            if (d2 < best || (d2 == best && k2 < bk)) { best = d2; bk = k2; }
        }
        int ov = ovf[s];
        ov |= __shfl_xor_sync(FULL, ov, 1);
        ov |= __shfl_xor_sync(FULL, ov, 2);
        if (tq == 0) {
            SBIDX[row] = (u16)bk;
            if (ov) SOVF[row] = 1;
        }
    }
    __syncthreads();

    // ---- epilogue: thread = row. gather, straight-through out, loss ----
    {
        const float* xrow = A32 + tid * ASTRIDE;
        int bidx;
        if (SOVF[tid]) {    // overflow fallback: exact full scan (rare)
            float best = 3.4e38f; bidx = 0;
            for (int k = 0; k < KCODES; k++) {
                float d = exact_d(xrow, weight + (size_t)k * DDIM, sx, SWN[k]);
                if (d < best) { best = d; bidx = k; }
            }
        } else {
            bidx = SBIDX[tid];
        }

        const float* qrow = weight + (size_t)bidx * DDIM;
        float* outp = out + (size_t)b * DDIM * HWSZ + hw0 + tid;
        float lloss = 0.f;
        #pragma unroll
        for (int c = 0; c < DDIM; c++) {
            float q = qrow[c];
            float x = xrow[c];
            float e = __fsub_rn(q, x);
            outp[(size_t)c * HWSZ] = __fadd_rn(x, e);
            lloss = fmaf(e, e, lloss);
        }

        __syncthreads();
        SX[tid] = lloss;
        __syncthreads();
        #pragma unroll
        for (int st = NTHREADS / 2; st > 0; st >>= 1) {
            if (tid < st) SX[tid] += SX[tid + st];
            __syncthreads();
        }
        if (tid == 0) g_partials[blockIdx.x] = SX[0];
    }
}

__global__ void loss_kernel(float* __restrict__ out, int out_size)
{
    __shared__ float red[256];
    const int tid = threadIdx.x;
    float s = 0.f;
    for (int i = tid; i < NTILES; i += 256) s += g_partials[i];
    red[tid] = s;
    __syncthreads();
    #pragma unroll
    for (int st = 128; st > 0; st >>= 1) {
        if (tid < st) red[tid] += red[tid + st];
        __syncthreads();
    }
    if (tid == 0) {
        float loss = red[0] * 1.25f / (float)((long long)NTOT * DDIM);
        for (long long i = (long long)NTOT * DDIM; i < out_size; i++)
            out[i] = loss;
    }
}

extern "C" void kernel_launch(void* const* d_in, const int* in_sizes, int n_in,
                              void* d_out, int out_size)
{
    const float* input  = (const float*)d_in[0];
    const float* weight = (const float*)d_in[1];
    float* out = (float*)d_out;

    cudaFuncSetAttribute(vq_mma_kernel, cudaFuncAttributeMaxDynamicSharedMemorySize, SMEM_TOTAL);
    vq_mma_kernel<<<NTILES, NTHREADS, SMEM_TOTAL>>>(input, weight, out);
    loss_kernel<<<1, 256>>>(out, out_size);
}

// round 5
// speedup vs baseline: 1.4387x; 1.4387x over previous
#include <cuda_runtime.h>

// VectorQuantizer: two-pass warp tf32 mma.sync (min, then threshold-collect)
// + exact fp32 re-score of queued candidates.
// inputs [32,64,64,64] f32 NCHW, weight [512,64] f32.
// out[0..N*D) = fl(x + fl(q-x)) NCHW; out[N*D..) = 1.25*mean((q-x)^2).

#define KCODES  512
#define DDIM    64
#define HWSZ    4096
#define NTOT    131072
#define TILE_M  256
#define NTILES  (NTOT / TILE_M)   // 512
#define NTHREADS 256
#define QCAP    4096

typedef unsigned int u32;
typedef unsigned long long u64;
typedef unsigned short u16;

__device__ float g_partials[NTILES];

// ---- smem layout (bytes) ----
#define BSTRIDE  520                               // u32 per k-row; bank = (8k+n)%32 conflict-free
#define OFF_B    0                                 // 64*520*4    = 133120
#define OFF_A    (64 * BSTRIDE * 4)                // 256*65*4    = 66560
#define ASTRIDE  65
#define OFF_SWN  (OFF_A + TILE_M * ASTRIDE * 4)    // 2048
#define OFF_SX   (OFF_SWN + 2048)                  // 1024
#define OFF_KEY  (OFF_SX + 1024)                   // 256*8 = 2048
#define OFF_QCNT (OFF_KEY + 2048)                  // 16
#define OFF_OVF  (OFF_QCNT + 16)                   // 256
#define OFF_QUE  (OFF_OVF + 256)                   // QCAP*4 = 16384
#define SMEM_TOTAL (OFF_QUE + QCAP * 4)            // 221456 B

// ---- scalar helpers ----
__device__ __forceinline__ u32 f2tf32(float f) {
    u32 r; asm("cvt.rna.tf32.f32 %0, %1;" : "=r"(r) : "f"(f)); return r;
}
__device__ __forceinline__ u64 ffma2(u64 a, u64 b, u64 c) {
    u64 d; asm("fma.rn.f32x2 %0, %1, %2, %3;" : "=l"(d) : "l"(a), "l"(b), "l"(c)); return d;
}
__device__ __forceinline__ u64 fadd2(u64 a, u64 b) {
    u64 d; asm("add.rn.f32x2 %0, %1, %2;" : "=l"(d) : "l"(a), "l"(b)); return d;
}
__device__ __forceinline__ u64 pack2(float lo, float hi) {
    u64 d; asm("mov.b64 %0, {%1, %2};" : "=l"(d) : "f"(lo), "f"(hi)); return d;
}
__device__ __forceinline__ void unpack2(u64 v, float& lo, float& hi) {
    asm("mov.b64 {%0, %1}, %2;" : "=f"(lo), "=f"(hi) : "l"(v));
}

#define MMA4(c, a, b0, b1)                                                      \
    asm volatile("mma.sync.aligned.m16n8k8.row.col.f32.tf32.tf32.f32 "          \
                 "{%0,%1,%2,%3}, {%4,%5,%6,%7}, {%8,%9}, {%0,%1,%2,%3};"        \
                 : "+f"((c)[0]), "+f"((c)[1]), "+f"((c)[2]), "+f"((c)[3])       \
                 : "r"((a)[0]), "r"((a)[1]), "r"((a)[2]), "r"((a)[3]),          \
                   "r"(b0), "r"(b1))

// exact fp32 score, bit-identical to the round-2 passing pipeline.
__device__ __forceinline__ float exact_d(const float* __restrict__ xrow,
                                         const float* __restrict__ wrow,
                                         float sx, float swn_k) {
    u64 a0 = 0ull, a1 = 0ull, a2 = 0ull, a3 = 0ull;
    #pragma unroll
    for (int j = 0; j < DDIM / 2; j += 4) {
        u64 x0 = pack2(xrow[2*(j+0)], xrow[2*(j+0)+1]);
        u64 x1 = pack2(xrow[2*(j+1)], xrow[2*(j+1)+1]);
        u64 x2 = pack2(xrow[2*(j+2)], xrow[2*(j+2)+1]);
        u64 x3 = pack2(xrow[2*(j+3)], xrow[2*(j+3)+1]);
        u64 w0 = pack2(wrow[2*(j+0)], wrow[2*(j+0)+1]);
        u64 w1 = pack2(wrow[2*(j+1)], wrow[2*(j+1)+1]);
        u64 w2 = pack2(wrow[2*(j+2)], wrow[2*(j+2)+1]);
        u64 w3 = pack2(wrow[2*(j+3)], wrow[2*(j+3)+1]);
        a0 = ffma2(x0, w0, a0);
        a1 = ffma2(x1, w1, a1);
        a2 = ffma2(x2, w2, a2);
        a3 = ffma2(x3, w3, a3);
    }
    a0 = fadd2(a0, a1);
    a2 = fadd2(a2, a3);
    a0 = fadd2(a0, a2);
    float lo, hi;
    unpack2(a0, lo, hi);
    float dot = __fadd_rn(lo, hi);
    float t = __fadd_rn(sx, swn_k);
    return __fsub_rn(t, __fmul_rn(2.0f, dot));
}

extern __shared__ char smem[];

// one 16-code chunk of MMAs (shared by pass 1 and pass 2 -> bit-identical dt)
__device__ __forceinline__ void chunk_mma(const u32* __restrict__ Bu,
                                          const u32 afr[2][8][4],
                                          int nb, int tq, int g,
                                          float acc[2][2][4]) {
    #pragma unroll
    for (int i = 0; i < 2; i++)
        #pragma unroll
        for (int j = 0; j < 2; j++)
            #pragma unroll
            for (int e = 0; e < 4; e++) acc[i][j][e] = 0.f;
    #pragma unroll
    for (int ks = 0; ks < 8; ks++) {
        const u32* bk0 = Bu + (ks * 8 + tq) * BSTRIDE + nb + g;
        const u32* bk1 = bk0 + 4 * BSTRIDE;
        u32 b0a = bk0[0], b0b = bk0[8];
        u32 b1a = bk1[0], b1b = bk1[8];
        MMA4(acc[0][0], afr[0][ks], b0a, b1a);
        MMA4(acc[0][1], afr[0][ks], b0b, b1b);
        MMA4(acc[1][0], afr[1][ks], b0a, b1a);
        MMA4(acc[1][1], afr[1][ks], b0b, b1b);
    }
}

__global__ void __launch_bounds__(NTHREADS, 1)
vq_mma_kernel(const float* __restrict__ input,
              const float* __restrict__ weight,
              float* __restrict__ out)
{
    u32*   Bu    = (u32*)(smem + OFF_B);
    float* A32   = (float*)(smem + OFF_A);
    float* SWN   = (float*)(smem + OFF_SWN);
    float* SX    = (float*)(smem + OFF_SX);
    u64*   KEY   = (u64*)(smem + OFF_KEY);
    u32*   QCNT  = (u32*)(smem + OFF_QCNT);
    unsigned char* SOVF = (unsigned char*)(smem + OFF_OVF);
    u32*   QUE   = (u32*)(smem + OFF_QUE);

    const int tid = threadIdx.x;
    const int b   = blockIdx.x >> 4;
    const int hw0 = (blockIdx.x & 15) * TILE_M;
    const float* inb = input + (size_t)b * DDIM * HWSZ + hw0 + tid;

    // ---- init bookkeeping ----
    KEY[tid] = ~0ull;
    SOVF[tid] = 0;
    if (tid == 0) *QCNT = 0;

    // ---- stage A (fp32) + exact sequential sx ----
    float sx = 0.f;
    {
        float* arow = A32 + tid * ASTRIDE;
        #pragma unroll
        for (int c = 0; c < DDIM; c++) {
            float v = inb[(size_t)c * HWSZ];
            arow[c] = v;
            sx = __fadd_rn(sx, __fmul_rn(v, v));
        }
        SX[tid] = sx;
    }

    // ---- stage B (tf32, [c][k] padded) + exact sequential norms ----
    #pragma unroll
    for (int r = 0; r < 2; r++) {
        const int k = tid + r * NTHREADS;
        const float4* wr = (const float4*)(weight + (size_t)k * DDIM);
        float s = 0.f;
        #pragma unroll
        for (int c4 = 0; c4 < DDIM / 4; c4++) {
            float4 wv = wr[c4];
            s = __fadd_rn(s, __fmul_rn(wv.x, wv.x));
            s = __fadd_rn(s, __fmul_rn(wv.y, wv.y));
            s = __fadd_rn(s, __fmul_rn(wv.z, wv.z));
            s = __fadd_rn(s, __fmul_rn(wv.w, wv.w));
            int c = c4 * 4;
            Bu[(c + 0) * BSTRIDE + k] = f2tf32(wv.x);
            Bu[(c + 1) * BSTRIDE + k] = f2tf32(wv.y);
            Bu[(c + 2) * BSTRIDE + k] = f2tf32(wv.z);
            Bu[(c + 3) * BSTRIDE + k] = f2tf32(wv.w);
        }
        SWN[k] = s;
    }
    __syncthreads();

    // ---- A fragments (tf32) ----
    const int lane  = tid & 31;
    const int g     = lane >> 2;
    const int tq    = lane & 3;
    const int rbase = (tid >> 5) * 32;

    u32 afr[2][8][4];
    #pragma unroll
    for (int mt = 0; mt < 2; mt++) {
        const float* r0 = A32 + (rbase + mt * 16 + g) * ASTRIDE;
        const float* r1 = r0 + 8 * ASTRIDE;
        #pragma unroll
        for (int ks = 0; ks < 8; ks++) {
            afr[mt][ks][0] = f2tf32(r0[ks * 8 + tq]);
            afr[mt][ks][1] = f2tf32(r1[ks * 8 + tq]);
            afr[mt][ks][2] = f2tf32(r0[ks * 8 + tq + 4]);
            afr[mt][ks][3] = f2tf32(r1[ks * 8 + tq + 4]);
        }
    }

    // slot s = mt*2 + (e>>1) ; row = rbase + mt*16 + (s&1)*8 + g
    float mrg[4], bmin[4];
    #pragma unroll
    for (int s = 0; s < 4; s++) {
        int row = rbase + (s >> 1) * 16 + (s & 1) * 8 + g;
        mrg[s]  = fmaf(sqrtf(SX[row]), 1e-4f, 5e-5f);
        bmin[s] = 3.4e38f;
    }

    // ================= PASS 1: min only (branchless) =================
    #pragma unroll 1
    for (int n2 = 0; n2 < 32; n2++) {
        const int nb = n2 * 16;
        float acc[2][2][4];
        chunk_mma(Bu, afr, nb, tq, g, acc);
        float swnc[2][2];
        swnc[0][0] = SWN[nb + tq * 2];
        swnc[0][1] = SWN[nb + tq * 2 + 1];
        swnc[1][0] = SWN[nb + 8 + tq * 2];
        swnc[1][1] = SWN[nb + 8 + tq * 2 + 1];
        #pragma unroll
        for (int mt = 0; mt < 2; mt++)
        #pragma unroll
        for (int nn = 0; nn < 2; nn++)
        #pragma unroll
        for (int e = 0; e < 4; e++) {
            const int s = mt * 2 + (e >> 1);
            float dt = fmaf(-2.f, acc[mt][nn][e], swnc[nn][e & 1]);
            bmin[s] = fminf(bmin[s], dt);
        }
    }

    // quad-merge min -> threshold
    const unsigned FULL = 0xffffffffu;
    float th[4];
    #pragma unroll
    for (int s = 0; s < 4; s++) {
        float bm = bmin[s];
        bm = fminf(bm, __shfl_xor_sync(FULL, bm, 1));
        bm = fminf(bm, __shfl_xor_sync(FULL, bm, 2));
        th[s] = bm + mrg[s];
    }

    // ================= PASS 2: recompute, collect into queue =================
    #pragma unroll 1
    for (int n2 = 0; n2 < 32; n2++) {
        const int nb = n2 * 16;
        float acc[2][2][4];
        chunk_mma(Bu, afr, nb, tq, g, acc);
        float swnc[2][2];
        swnc[0][0] = SWN[nb + tq * 2];
        swnc[0][1] = SWN[nb + tq * 2 + 1];
        swnc[1][0] = SWN[nb + 8 + tq * 2];
        swnc[1][1] = SWN[nb + 8 + tq * 2 + 1];
        #pragma unroll
        for (int mt = 0; mt < 2; mt++)
        #pragma unroll
        for (int nn = 0; nn < 2; nn++)
        #pragma unroll
        for (int e = 0; e < 4; e++) {
            const int s   = mt * 2 + (e >> 1);
            const int col = nb + nn * 8 + tq * 2 + (e & 1);
            const int row = rbase + mt * 16 + (e >> 1) * 8 + g;
            float dt = fmaf(-2.f, acc[mt][nn][e], swnc[nn][e & 1]);
            bool take = (dt <= th[s]);
            unsigned m = __ballot_sync(FULL, take);
            if (m) {
                int leader = __ffs(m) - 1;
                u32 base = 0;
                if (lane == leader) base = atomicAdd(QCNT, (u32)__popc(m));
                base = __shfl_sync(FULL, base, leader);
                if (take) {
                    u32 pos = base + (u32)__popc(m & ((1u << lane) - 1u));
                    if (pos < QCAP) QUE[pos] = ((u32)row << 16) | (u32)col;
                    else SOVF[row] = 1;
                }
            }
        }
    }
    __syncthreads();

    // ================= exact rescore of queue (cooperative, no divergence) ====
    {
        int qn = *QCNT;
        if (qn > QCAP) qn = QCAP;
        for (int i = tid; i < qn; i += NTHREADS) {
            u32 e = QUE[i];
            int row = e >> 16;
            int k   = e & 0xffff;
            float d = exact_d(A32 + row * ASTRIDE, weight + (size_t)k * DDIM,
                              SX[row], SWN[k]);
            u64 key = ((u64)__float_as_uint(d) << 16) | (u64)k;
            atomicMin(&KEY[row], key);
        }
    }
    __syncthreads();

    // ================= epilogue: gather, straight-through out, loss ==========
    {
        const float* xrow = A32 + tid * ASTRIDE;
        int bidx;
        if (SOVF[tid]) {   // overflow fallback: full exact scan (rare)
            float best = 3.4e38f; bidx = 0;
            for (int k = 0; k < KCODES; k++) {
                float d = exact_d(xrow, weight + (size_t)k * DDIM, sx, SWN[k]);
                if (d < best) { best = d; bidx = k; }
            }
        } else {
            bidx = (int)(KEY[tid] & 0xffffull);
        }

        const float* qrow = weight + (size_t)bidx * DDIM;
        float* outp = out + (size_t)b * DDIM * HWSZ + hw0 + tid;
        float lloss = 0.f;
        #pragma unroll
        for (int c = 0; c < DDIM; c++) {
            float q = qrow[c];
            float x = xrow[c];
            float e = __fsub_rn(q, x);
            outp[(size_t)c * HWSZ] = __fadd_rn(x, e);
            lloss = fmaf(e, e, lloss);
        }

        __syncthreads();
        SX[tid] = lloss;
        __syncthreads();
        #pragma unroll
        for (int st = NTHREADS / 2; st > 0; st >>= 1) {
            if (tid < st) SX[tid] += SX[tid + st];
            __syncthreads();
        }
        if (tid == 0) g_partials[blockIdx.x] = SX[0];
    }
}

__global__ void loss_kernel(float* __restrict__ out, int out_size)
{
    __shared__ float red[256];
    const int tid = threadIdx.x;
    float s = 0.f;
    for (int i = tid; i < NTILES; i += 256) s += g_partials[i];
    red[tid] = s;
    __syncthreads();
    #pragma unroll
    for (int st = 128; st > 0; st >>= 1) {
        if (tid < st) red[tid] += red[tid + st];
        __syncthreads();
    }
    if (tid == 0) {
        float loss = red[0] * 1.25f / (float)((long long)NTOT * DDIM);
        for (long long i = (long long)NTOT * DDIM; i < out_size; i++)
            out[i] = loss;
    }
}

extern "C" void kernel_launch(void* const* d_in, const int* in_sizes, int n_in,
                              void* d_out, int out_size)
{
    const float* input  = (const float*)d_in[0];
    const float* weight = (const float*)d_in[1];
    float* out = (float*)d_out;

    cudaFuncSetAttribute(vq_mma_kernel, cudaFuncAttributeMaxDynamicSharedMemorySize, SMEM_TOTAL);
    vq_mma_kernel<<<NTILES, NTHREADS, SMEM_TOTAL>>>(input, weight, out);
    loss_kernel<<<1, 256>>>(out, out_size);
}